// round 1
// baseline (speedup 1.0000x reference)
#include <cuda_runtime.h>

#define NB 16
#define NS 4096
#define NE 8
#define NTOK (NB*NS)
#define TQ 1024

// scratch (device globals: no allocation allowed)
__device__ float g_qrow[NTOK*NE];      // [b][s][w]  row-major features
__device__ float g_qcol[NB*NE*NS];     // [b][w][t]  transposed for packed loads
__device__ float g_att[NTOK*NE];       // attention output [b][s][e]

typedef unsigned long long u64;

__device__ __forceinline__ u64 pk2(float lo, float hi){u64 r; asm("mov.b64 %0,{%1,%2};":"=l"(r):"f"(lo),"f"(hi)); return r;}
__device__ __forceinline__ float2 upk2(u64 v){float2 f; asm("mov.b64 {%0,%1},%2;":"=f"(f.x),"=f"(f.y):"l"(v)); return f;}
__device__ __forceinline__ u64 fma2(u64 a,u64 b,u64 c){u64 d; asm("fma.rn.f32x2 %0,%1,%2,%3;":"=l"(d):"l"(a),"l"(b),"l"(c)); return d;}
__device__ __forceinline__ u64 mul2(u64 a,u64 b){u64 d; asm("mul.rn.f32x2 %0,%1,%2;":"=l"(d):"l"(a),"l"(b)); return d;}
__device__ __forceinline__ u64 add2(u64 a,u64 b){u64 d; asm("add.rn.f32x2 %0,%1,%2;":"=l"(d):"l"(a),"l"(b)); return d;}

// ---------------------------------------------------------------------------
// Kernel 1: quantum features.  q[w] = prefix products of cos(x+theta).
// ---------------------------------------------------------------------------
__global__ void feat_kernel(const float* __restrict__ x, const float* __restrict__ theta)
{
    int tok = blockIdx.x*blockDim.x + threadIdx.x;
    float th[8];
    #pragma unroll
    for(int w=0;w<8;w++) th[w] = __ldg(&theta[w]);
    float4 x0 = *(const float4*)&x[tok*8];
    float4 x1 = *(const float4*)&x[tok*8+4];
    float c[8];
    c[0]=cosf(x0.x+th[0]); c[1]=cosf(x0.y+th[1]); c[2]=cosf(x0.z+th[2]); c[3]=cosf(x0.w+th[3]);
    c[4]=cosf(x1.x+th[4]); c[5]=cosf(x1.y+th[5]); c[6]=cosf(x1.z+th[6]); c[7]=cosf(x1.w+th[7]);
    float q[8];
    float p = c[0];
    #pragma unroll
    for(int w=1;w<8;w++){ p *= c[w]; q[w] = p; }
    float s = c[1];
    #pragma unroll
    for(int w=2;w<8;w++) s *= c[w];
    q[0] = s;                              // c1*...*c7 (wire 0: CNOT-ring inverse image)
    *(float4*)&g_qrow[tok*8]   = make_float4(q[0],q[1],q[2],q[3]);
    *(float4*)&g_qrow[tok*8+4] = make_float4(q[4],q[5],q[6],q[7]);
    int b = tok >> 12, t = tok & (NS-1);
    #pragma unroll
    for(int w=0;w<8;w++) g_qcol[(b*8+w)*NS + t] = q[w];
}

// ---------------------------------------------------------------------------
// Kernel 2: streaming softmax attention, fp32, packed f32x2, FFMA-only exp.
//   score = (q_s . q_t)/sqrt(2) in [-5.66, 5.66]  =>  no max-subtraction.
//   exp(d) = (exp(d/8))^8, exp(u) = deg-6 Taylor on |u|<=0.707.
//   1/(8*sqrt2) folded into q_s. One thread = one row s; t streamed via smem.
// ---------------------------------------------------------------------------
__global__ void __launch_bounds__(128) attn_kernel()
{
    __shared__ float sq[8*TQ];             // [w][t] chunk, 32 KB
    const int b   = blockIdx.y;
    const int row = (blockIdx.x<<7) + threadIdx.x;
    const float SC = 0.08838834764831845f; // 1/(8*sqrt(2))

    u64 qs[8];
    #pragma unroll
    for(int w=0;w<8;w++){ float v = g_qrow[(b*NS+row)*8+w]*SC; qs[w]=pk2(v,v); }
    u64 acc[8];
    #pragma unroll
    for(int w=0;w<8;w++) acc[w]=pk2(0.f,0.f);
    u64 den = pk2(0.f,0.f);
    const u64 C6=pk2(1.f/720,1.f/720), C5=pk2(1.f/120,1.f/120), C4=pk2(1.f/24,1.f/24),
              C3=pk2(1.f/6,1.f/6),     C2=pk2(0.5f,0.5f),       C1=pk2(1.f,1.f),
              C0=pk2(1.f,1.f);
    const float* qc = &g_qcol[b*8*NS];

    for(int ch=0; ch<NS/TQ; ch++){
        // cooperative chunk load (all CTA threads), float4
        #pragma unroll
        for(int i=threadIdx.x; i<8*TQ/4; i+=128){
            int w = i >> 8, t4 = i & 255;  // TQ/4 == 256
            ((float4*)sq)[(w<<8)+t4] = *(const float4*)&qc[w*NS + ch*TQ + (t4<<2)];
        }
        __syncthreads();
        #pragma unroll 2
        for(int tp=0; tp<TQ/2; tp++){
            u64 qt[8];
            #pragma unroll
            for(int w=0;w<8;w++) qt[w] = *(const u64*)&sq[w*TQ + (tp<<1)];
            u64 u = mul2(qs[0],qt[0]);
            #pragma unroll
            for(int w=1;w<8;w++) u = fma2(qs[w],qt[w],u);   // u = score/8, |u|<=0.707
            u64 p = fma2(u,C6,C5);                          // exp(u), Taylor-6
            p = fma2(p,u,C4);
            p = fma2(p,u,C3);
            p = fma2(p,u,C2);
            p = fma2(p,u,C1);
            p = fma2(p,u,C0);
            p = mul2(p,p); p = mul2(p,p); p = mul2(p,p);    // ^8 -> exp(score)
            den = add2(den,p);
            #pragma unroll
            for(int w=0;w<8;w++) acc[w] = fma2(p,qt[w],acc[w]);
        }
        __syncthreads();
    }

    float2 d2 = upk2(den);
    float inv = 1.0f/(d2.x + d2.y);
    float o[8];
    #pragma unroll
    for(int w=0;w<8;w++){ float2 a = upk2(acc[w]); o[w]=(a.x+a.y)*inv; }
    *(float4*)&g_att[(b*NS+row)*8]   = make_float4(o[0],o[1],o[2],o[3]);
    *(float4*)&g_att[(b*NS+row)*8+4] = make_float4(o[4],o[5],o[6],o[7]);
}

// ---------------------------------------------------------------------------
// Kernel 3: swapaxes(1,2).reshape scramble + out @ W^T + b.
//   final[b,i,e'] = b[e'] + sum_j att[b, 8*(i%512)+j, i>>9] * W[e',j]
// ---------------------------------------------------------------------------
__global__ void epi_kernel(const float* __restrict__ W, const float* __restrict__ bias,
                           float* __restrict__ out)
{
    int idx = blockIdx.x*blockDim.x + threadIdx.x;   // b*NS + i
    int i  = idx & (NS-1);
    int b  = idx >> 12;
    int e  = i >> 9;
    int s0 = (i & 511) << 3;
    const float* g = &g_att[(b*NS + s0)*8 + e];
    float y[8];
    #pragma unroll
    for(int j=0;j<8;j++) y[j] = g[j*8];
    float r[8];
    #pragma unroll
    for(int ep=0;ep<8;ep++){
        float a = __ldg(&bias[ep]);
        #pragma unroll
        for(int j=0;j<8;j++) a = fmaf(y[j], __ldg(&W[ep*8+j]), a);
        r[ep]=a;
    }
    *(float4*)&out[idx*8]   = make_float4(r[0],r[1],r[2],r[3]);
    *(float4*)&out[idx*8+4] = make_float4(r[4],r[5],r[6],r[7]);
}

extern "C" void kernel_launch(void* const* d_in, const int* in_sizes, int n_in,
                              void* d_out, int out_size)
{
    const float* x     = (const float*)d_in[0];
    const float* theta = (const float*)d_in[1];
    const float* w     = (const float*)d_in[2];
    const float* bias  = (const float*)d_in[3];
    float* out = (float*)d_out;

    feat_kernel<<<NTOK/256, 256>>>(x, theta);
    dim3 g(NS/128, NB);
    attn_kernel<<<g, 128>>>();
    epi_kernel<<<NTOK/256, 256>>>(w, bias, out);
}

// round 2
// speedup vs baseline: 1.3680x; 1.3680x over previous
#include <cuda_runtime.h>

#define NB 16
#define NS 4096
#define NE 8
#define NTOK (NB*NS)
#define TQ 1024

// scratch (device globals: no allocation allowed)
__device__ float g_qrow[NTOK*NE];      // [b][s][w]  row-major features (pre-scaled for attn)
__device__ float g_qcol[NB*NE*NS];     // [b][w][t]  transposed for packed loads
__device__ float g_att[NTOK*NE];       // attention output [b][s][e]

typedef unsigned long long u64;

__device__ __forceinline__ u64 pk2(float lo, float hi){u64 r; asm("mov.b64 %0,{%1,%2};":"=l"(r):"f"(lo),"f"(hi)); return r;}
__device__ __forceinline__ float2 upk2(u64 v){float2 f; asm("mov.b64 {%0,%1},%2;":"=f"(f.x),"=f"(f.y):"l"(v)); return f;}
__device__ __forceinline__ u64 fma2(u64 a,u64 b,u64 c){u64 d; asm("fma.rn.f32x2 %0,%1,%2,%3;":"=l"(d):"l"(a),"l"(b),"l"(c)); return d;}
__device__ __forceinline__ u64 mul2(u64 a,u64 b){u64 d; asm("mul.rn.f32x2 %0,%1,%2;":"=l"(d):"l"(a),"l"(b)); return d;}
__device__ __forceinline__ u64 add2(u64 a,u64 b){u64 d; asm("add.rn.f32x2 %0,%1,%2;":"=l"(d):"l"(a),"l"(b)); return d;}
__device__ __forceinline__ float ex2f(float x){float r; asm("ex2.approx.ftz.f32 %0,%1;":"=f"(r):"f"(x)); return r;}

// ---------------------------------------------------------------------------
// Kernel 1: quantum features.  q[w] = prefix products of cos(x+theta).
//   (CNOT-ring inverse image: q[0] = c1*...*c7, q[w>=1] = c0*...*cw)
// ---------------------------------------------------------------------------
__global__ void feat_kernel(const float* __restrict__ x, const float* __restrict__ theta)
{
    int tok = blockIdx.x*blockDim.x + threadIdx.x;
    float th[8];
    #pragma unroll
    for(int w=0;w<8;w++) th[w] = __ldg(&theta[w]);
    float4 x0 = *(const float4*)&x[tok*8];
    float4 x1 = *(const float4*)&x[tok*8+4];
    float c[8];
    c[0]=cosf(x0.x+th[0]); c[1]=cosf(x0.y+th[1]); c[2]=cosf(x0.z+th[2]); c[3]=cosf(x0.w+th[3]);
    c[4]=cosf(x1.x+th[4]); c[5]=cosf(x1.y+th[5]); c[6]=cosf(x1.z+th[6]); c[7]=cosf(x1.w+th[7]);
    float q[8];
    float p = c[0];
    #pragma unroll
    for(int w=1;w<8;w++){ p *= c[w]; q[w] = p; }
    float s = c[1];
    #pragma unroll
    for(int w=2;w<8;w++) s *= c[w];
    q[0] = s;
    *(float4*)&g_qrow[tok*8]   = make_float4(q[0],q[1],q[2],q[3]);
    *(float4*)&g_qrow[tok*8+4] = make_float4(q[4],q[5],q[6],q[7]);
    int b = tok >> 12, t = tok & (NS-1);
    #pragma unroll
    for(int w=0;w<8;w++) g_qcol[(b*8+w)*NS + t] = q[w];
}

// ---------------------------------------------------------------------------
// Kernel 2: streaming softmax attention.
//   score*log2(e) = (qs_scaled . qt), p = ex2(.) on the MUFU pipe.
//   |score| <= 8/sqrt(2) => no max-subtraction needed.
//   FMA pipe per packed t-pair: 8 dot + 8 acc + 1 den = 17 f32x2 ops.
// ---------------------------------------------------------------------------
__global__ void __launch_bounds__(128) attn_kernel()
{
    __shared__ float sq[8*TQ];             // [w][t] chunk, 32 KB
    const int b   = blockIdx.y;
    const int row = (blockIdx.x<<7) + threadIdx.x;
    const float SC = 1.02013946f;          // log2(e)/sqrt(2)

    u64 qs[8];
    #pragma unroll
    for(int w=0;w<8;w++){ float v = g_qrow[(b*NS+row)*8+w]*SC; qs[w]=pk2(v,v); }
    u64 acc[8];
    #pragma unroll
    for(int w=0;w<8;w++) acc[w]=pk2(0.f,0.f);
    u64 den = pk2(0.f,0.f);
    const float* qc = &g_qcol[b*8*NS];

    for(int ch=0; ch<NS/TQ; ch++){
        // cooperative chunk load (all CTA threads), float4
        #pragma unroll
        for(int i=threadIdx.x; i<8*TQ/4; i+=128){
            int w = i >> 8, t4 = i & 255;  // TQ/4 == 256
            ((float4*)sq)[(w<<8)+t4] = *(const float4*)&qc[w*NS + ch*TQ + (t4<<2)];
        }
        __syncthreads();
        #pragma unroll 2
        for(int t4=0; t4<TQ/4; t4++){
            u64 qlo[8], qhi[8];
            #pragma unroll
            for(int w=0;w<8;w++){
                float4 f = *(const float4*)&sq[w*TQ + (t4<<2)];
                qlo[w]=pk2(f.x,f.y); qhi[w]=pk2(f.z,f.w);
            }
            u64 u0 = mul2(qs[0],qlo[0]);
            u64 u1 = mul2(qs[0],qhi[0]);
            #pragma unroll
            for(int w=1;w<8;w++){
                u0 = fma2(qs[w],qlo[w],u0);
                u1 = fma2(qs[w],qhi[w],u1);
            }
            float2 a = upk2(u0), c = upk2(u1);
            u64 P0 = pk2(ex2f(a.x), ex2f(a.y));   // MUFU pipe
            u64 P1 = pk2(ex2f(c.x), ex2f(c.y));
            den = add2(den,P0);
            den = add2(den,P1);
            #pragma unroll
            for(int w=0;w<8;w++){
                acc[w] = fma2(P0,qlo[w],acc[w]);
                acc[w] = fma2(P1,qhi[w],acc[w]);
            }
        }
        __syncthreads();
    }

    float2 d2 = upk2(den);
    float inv = 1.0f/(d2.x + d2.y);
    float o[8];
    #pragma unroll
    for(int w=0;w<8;w++){ float2 a = upk2(acc[w]); o[w]=(a.x+a.y)*inv; }
    *(float4*)&g_att[(b*NS+row)*8]   = make_float4(o[0],o[1],o[2],o[3]);
    *(float4*)&g_att[(b*NS+row)*8+4] = make_float4(o[4],o[5],o[6],o[7]);
}

// ---------------------------------------------------------------------------
// Kernel 3: swapaxes(1,2).reshape scramble + out @ W^T + b.
//   final[b,i,e'] = b[e'] + sum_j att[b, 8*(i%512)+j, i>>9] * W[e',j]
// ---------------------------------------------------------------------------
__global__ void epi_kernel(const float* __restrict__ W, const float* __restrict__ bias,
                           float* __restrict__ out)
{
    int idx = blockIdx.x*blockDim.x + threadIdx.x;   // b*NS + i
    int i  = idx & (NS-1);
    int b  = idx >> 12;
    int e  = i >> 9;
    int s0 = (i & 511) << 3;
    const float* g = &g_att[(b*NS + s0)*8 + e];
    float y[8];
    #pragma unroll
    for(int j=0;j<8;j++) y[j] = g[j*8];
    float r[8];
    #pragma unroll
    for(int ep=0;ep<8;ep++){
        float a = __ldg(&bias[ep]);
        #pragma unroll
        for(int j=0;j<8;j++) a = fmaf(y[j], __ldg(&W[ep*8+j]), a);
        r[ep]=a;
    }
    *(float4*)&out[idx*8]   = make_float4(r[0],r[1],r[2],r[3]);
    *(float4*)&out[idx*8+4] = make_float4(r[4],r[5],r[6],r[7]);
}

extern "C" void kernel_launch(void* const* d_in, const int* in_sizes, int n_in,
                              void* d_out, int out_size)
{
    const float* x     = (const float*)d_in[0];
    const float* theta = (const float*)d_in[1];
    const float* w     = (const float*)d_in[2];
    const float* bias  = (const float*)d_in[3];
    float* out = (float*)d_out;

    feat_kernel<<<NTOK/256, 256>>>(x, theta);
    dim3 g(NS/128, NB);
    attn_kernel<<<g, 128>>>();
    epi_kernel<<<NTOK/256, 256>>>(w, bias, out);
}

// round 3
// speedup vs baseline: 1.3719x; 1.0029x over previous
#include <cuda_runtime.h>

#define NB 16
#define NS 4096
#define NE 8
#define NTOK (NB*NS)
#define TQ 1024
#define ATTN_THREADS 64

// scratch (device globals: no allocation allowed)
__device__ float g_qrow[NTOK*NE];      // [b][s][w]  row-major features
__device__ float g_qcol[NB*NE*NS];     // [b][w][t]  transposed for packed loads
__device__ float g_att[NTOK*NE];       // attention output [b][s][e]

typedef unsigned long long u64;

__device__ __forceinline__ u64 pk2(float lo, float hi){u64 r; asm("mov.b64 %0,{%1,%2};":"=l"(r):"f"(lo),"f"(hi)); return r;}
__device__ __forceinline__ float2 upk2(u64 v){float2 f; asm("mov.b64 {%0,%1},%2;":"=f"(f.x),"=f"(f.y):"l"(v)); return f;}
__device__ __forceinline__ u64 fma2(u64 a,u64 b,u64 c){u64 d; asm("fma.rn.f32x2 %0,%1,%2,%3;":"=l"(d):"l"(a),"l"(b),"l"(c)); return d;}
__device__ __forceinline__ u64 mul2(u64 a,u64 b){u64 d; asm("mul.rn.f32x2 %0,%1,%2;":"=l"(d):"l"(a),"l"(b)); return d;}
__device__ __forceinline__ u64 add2(u64 a,u64 b){u64 d; asm("add.rn.f32x2 %0,%1,%2;":"=l"(d):"l"(a),"l"(b)); return d;}
__device__ __forceinline__ float ex2f(float x){float r; asm("ex2.approx.ftz.f32 %0,%1;":"=f"(r):"f"(x)); return r;}

// ---------------------------------------------------------------------------
// Kernel 1: quantum features.  q[w] = prefix products of cos(x+theta).
//   (CNOT-ring inverse image: q[0] = c1*...*c7, q[w>=1] = c0*...*cw)
// ---------------------------------------------------------------------------
__global__ void feat_kernel(const float* __restrict__ x, const float* __restrict__ theta)
{
    int tok = blockIdx.x*blockDim.x + threadIdx.x;
    float th[8];
    #pragma unroll
    for(int w=0;w<8;w++) th[w] = __ldg(&theta[w]);
    float4 x0 = *(const float4*)&x[tok*8];
    float4 x1 = *(const float4*)&x[tok*8+4];
    float c[8];
    c[0]=__cosf(x0.x+th[0]); c[1]=__cosf(x0.y+th[1]); c[2]=__cosf(x0.z+th[2]); c[3]=__cosf(x0.w+th[3]);
    c[4]=__cosf(x1.x+th[4]); c[5]=__cosf(x1.y+th[5]); c[6]=__cosf(x1.z+th[6]); c[7]=__cosf(x1.w+th[7]);
    float q[8];
    float p = c[0];
    #pragma unroll
    for(int w=1;w<8;w++){ p *= c[w]; q[w] = p; }
    float s = c[1];
    #pragma unroll
    for(int w=2;w<8;w++) s *= c[w];
    q[0] = s;
    *(float4*)&g_qrow[tok*8]   = make_float4(q[0],q[1],q[2],q[3]);
    *(float4*)&g_qrow[tok*8+4] = make_float4(q[4],q[5],q[6],q[7]);
    int b = tok >> 12, t = tok & (NS-1);
    #pragma unroll
    for(int w=0;w<8;w++) g_qcol[(b*8+w)*NS + t] = q[w];
}

// ---------------------------------------------------------------------------
// Kernel 2: streaming softmax attention.
//   score*log2(e) = (qs_scaled . qt), p = ex2(.) on the MUFU pipe.
//   |score| <= 8/sqrt(2) => no max-subtraction needed.
//   qt loaded as ulonglong2 (LDS.128 -> packed f32x2 operands, zero repack MOVs).
//   64-thread CTAs, 1024 CTAs for ~perfect wave balance.
// ---------------------------------------------------------------------------
__global__ void __launch_bounds__(ATTN_THREADS) attn_kernel()
{
    __shared__ __align__(16) float sq[8*TQ];   // [w][t] chunk, 32 KB
    const int b   = blockIdx.y;
    const int row = blockIdx.x*ATTN_THREADS + threadIdx.x;
    const float SC = 1.02013946f;              // log2(e)/sqrt(2)

    u64 qs[8];
    #pragma unroll
    for(int w=0;w<8;w++){ float v = g_qrow[(b*NS+row)*8+w]*SC; qs[w]=pk2(v,v); }
    u64 acc[8];
    #pragma unroll
    for(int w=0;w<8;w++) acc[w]=pk2(0.f,0.f);
    u64 den0 = pk2(0.f,0.f), den1 = pk2(0.f,0.f);
    const float* qc = &g_qcol[b*8*NS];

    for(int ch=0; ch<NS/TQ; ch++){
        // cooperative chunk load, float4
        #pragma unroll
        for(int i=threadIdx.x; i<8*TQ/4; i+=ATTN_THREADS){
            int w = i >> 8, t4 = i & 255;      // TQ/4 == 256
            ((float4*)sq)[(w<<8)+t4] = *(const float4*)&qc[w*NS + ch*TQ + (t4<<2)];
        }
        __syncthreads();
        #pragma unroll 4
        for(int t4=0; t4<TQ/4; t4++){
            u64 qlo[8], qhi[8];
            #pragma unroll
            for(int w=0;w<8;w++){
                ulonglong2 v = *(const ulonglong2*)&sq[w*TQ + (t4<<2)];
                qlo[w]=v.x; qhi[w]=v.y;
            }
            u64 u0 = mul2(qs[0],qlo[0]);
            u64 u1 = mul2(qs[0],qhi[0]);
            #pragma unroll
            for(int w=1;w<8;w++){
                u0 = fma2(qs[w],qlo[w],u0);
                u1 = fma2(qs[w],qhi[w],u1);
            }
            float2 a = upk2(u0), c = upk2(u1);
            u64 P0 = pk2(ex2f(a.x), ex2f(a.y));   // MUFU pipe
            u64 P1 = pk2(ex2f(c.x), ex2f(c.y));
            den0 = add2(den0,P0);
            den1 = add2(den1,P1);
            #pragma unroll
            for(int w=0;w<8;w++){
                acc[w] = fma2(P0,qlo[w],acc[w]);
                acc[w] = fma2(P1,qhi[w],acc[w]);
            }
        }
        __syncthreads();
    }

    float2 da = upk2(den0), db = upk2(den1);
    float inv = 1.0f/((da.x + da.y) + (db.x + db.y));
    float o[8];
    #pragma unroll
    for(int w=0;w<8;w++){ float2 a = upk2(acc[w]); o[w]=(a.x+a.y)*inv; }
    *(float4*)&g_att[(b*NS+row)*8]   = make_float4(o[0],o[1],o[2],o[3]);
    *(float4*)&g_att[(b*NS+row)*8+4] = make_float4(o[4],o[5],o[6],o[7]);
}

// ---------------------------------------------------------------------------
// Kernel 3: swapaxes(1,2).reshape scramble + out @ W^T + b.
//   final[b,i,e'] = b[e'] + sum_j att[b, 8*(i%512)+j, i>>9] * W[e',j]
// ---------------------------------------------------------------------------
__global__ void epi_kernel(const float* __restrict__ W, const float* __restrict__ bias,
                           float* __restrict__ out)
{
    int idx = blockIdx.x*blockDim.x + threadIdx.x;   // b*NS + i
    int i  = idx & (NS-1);
    int b  = idx >> 12;
    int e  = i >> 9;
    int s0 = (i & 511) << 3;
    const float* g = &g_att[(b*NS + s0)*8 + e];
    float y[8];
    #pragma unroll
    for(int j=0;j<8;j++) y[j] = g[j*8];
    float r[8];
    #pragma unroll
    for(int ep=0;ep<8;ep++){
        float a = __ldg(&bias[ep]);
        #pragma unroll
        for(int j=0;j<8;j++) a = fmaf(y[j], __ldg(&W[ep*8+j]), a);
        r[ep]=a;
    }
    *(float4*)&out[idx*8]   = make_float4(r[0],r[1],r[2],r[3]);
    *(float4*)&out[idx*8+4] = make_float4(r[4],r[5],r[6],r[7]);
}

extern "C" void kernel_launch(void* const* d_in, const int* in_sizes, int n_in,
                              void* d_out, int out_size)
{
    const float* x     = (const float*)d_in[0];
    const float* theta = (const float*)d_in[1];
    const float* w     = (const float*)d_in[2];
    const float* bias  = (const float*)d_in[3];
    float* out = (float*)d_out;

    feat_kernel<<<NTOK/256, 256>>>(x, theta);
    dim3 g(NS/ATTN_THREADS, NB);
    attn_kernel<<<g, ATTN_THREADS>>>();
    epi_kernel<<<NTOK/256, 256>>>(w, bias, out);
}